// round 17
// baseline (speedup 1.0000x reference)
#include <cuda_runtime.h>
#include <cuda_bf16.h>
#include <mma.h>
#include <math.h>

#define H   128
#define GG  20
#define KNN 32
#define MAXN 24000
#define MAXE (MAXN*KNN)

using namespace nvcuda;

// ---------------- helpers ----------------------------------------------------
__device__ __forceinline__ unsigned smem_u32(const void* p) {
    unsigned a;
    asm("{ .reg .u64 t; cvta.to.shared.u64 t, %1; cvt.u32.u64 %0, t; }" : "=r"(a) : "l"(p));
    return a;
}
__device__ __forceinline__ void cp16(unsigned dst, const void* src) {
    asm volatile("cp.async.cg.shared.global [%0], [%1], 16;" :: "r"(dst), "l"(src) : "memory");
}

// ---------------- scratch ----------------------------------------------------
__device__ __align__(16) float g_h  [MAXN*H];
__device__ __align__(16) float g_A  [MAXN*H];
__device__ __align__(16) float g_B  [MAXN*H];
__device__ __align__(16) float g_mi [MAXN*H];
__device__ int   g_nbr[MAXE];
__device__ float g_attr[(size_t)MAXE*GG];
__device__ float g_pre[16*H];
__device__ __align__(16) unsigned short g_w2bf[3*2*16384];
__device__ __align__(16) unsigned short g_w1ebf[3*2*4096];
__device__ __align__(16) unsigned short g_w1ab[3*2*256*144];
__device__ __align__(16) unsigned short g_w1nb[3*2*128*272];
__device__ __align__(16) unsigned short g_w2nb[3*2*128*144];

// ---------------- K0: merged weight bake + g_pre zero ------------------------
__global__ void prep_kernel(const float* __restrict__ edge_w2, const float* __restrict__ edge_w1,
                            const float* __restrict__ edge_b1,
                            const float* __restrict__ nw1, const float* __restrict__ nb1,
                            const float* __restrict__ nw2, const float* __restrict__ nb2)
{
    int bid = blockIdx.x, k = threadIdx.x;
    if (bid < 384) {                       // W2^T + W1e images
        int l = bid >> 7, nr = bid & 127;
        if (k < 128) {
            float v = edge_w2[((size_t)l*H + k)*H + nr];
            __nv_bfloat16 hb = __float2bfloat16(v);
            __nv_bfloat16 lb = __float2bfloat16(v - __bfloat162float(hb));
            g_w2bf[(l*2+0)*16384 + nr*128 + k] = __bfloat16_as_ushort(hb);
            g_w2bf[(l*2+1)*16384 + nr*128 + k] = __bfloat16_as_ushort(lb);
        }
        if (k < 32) {
            float w = (k < GG) ? edge_w1[(size_t)l*276*H + k*H + nr] : 0.f;
            __nv_bfloat16 wh = __float2bfloat16(w);
            __nv_bfloat16 wl = __float2bfloat16(w - __bfloat162float(wh));
            g_w1ebf[(l*2+0)*4096 + nr*32 + k] = __bfloat16_as_ushort(wh);
            g_w1ebf[(l*2+1)*4096 + nr*32 + k] = __bfloat16_as_ushort(wl);
        }
    } else if (bid < 1152) {               // augmented [W1i|W1j]
        int b2 = bid - 384;
        int l = b2 >> 8, n = b2 & 255;
        if (k < 144) {
            float v = 0.f;
            if (k < 128) {
                v = (n < 128) ? edge_w1[(size_t)l*276*H + (GG+k)*H + n]
                              : edge_w1[(size_t)l*276*H + (GG+128+k)*H + (n-128)];
            } else if (k == 128 && n < 128) {
                v = edge_b1[l*H + n];
            }
            __nv_bfloat16 hb = __float2bfloat16(v);
            __nv_bfloat16 lb = __float2bfloat16(v - __bfloat162float(hb));
            g_w1ab[((size_t)(l*2+0)*256 + n)*144 + k] = __bfloat16_as_ushort(hb);
            g_w1ab[((size_t)(l*2+1)*256 + n)*144 + k] = __bfloat16_as_ushort(lb);
        }
    } else if (bid < 1536) {               // node W1aug
        int b2 = bid - 1152;
        int l = b2 >> 7, n = b2 & 127;
        if (k < 272) {
            float v = 0.f;
            if (k < 256)       v = nw1[(size_t)l*256*H + (size_t)k*H + n];
            else if (k == 256) v = nb1[l*H + n];
            __nv_bfloat16 hb = __float2bfloat16(v);
            __nv_bfloat16 lb = __float2bfloat16(v - __bfloat162float(hb));
            g_w1nb[((size_t)(l*2+0)*128 + n)*272 + k] = __bfloat16_as_ushort(hb);
            g_w1nb[((size_t)(l*2+1)*128 + n)*272 + k] = __bfloat16_as_ushort(lb);
        }
    } else if (bid < 1920) {               // node W2aug
        int b2 = bid - 1536;
        int l = b2 >> 7, n = b2 & 127;
        if (k < 144) {
            float v = 0.f;
            if (k < 128)       v = nw2[(size_t)l*H*H + (size_t)k*H + n];
            else if (k == 128) v = nb2[l*H + n];
            __nv_bfloat16 hb = __float2bfloat16(v);
            __nv_bfloat16 lb = __float2bfloat16(v - __bfloat162float(hb));
            g_w2nb[((size_t)(l*2+0)*128 + n)*144 + k] = __bfloat16_as_ushort(hb);
            g_w2nb[((size_t)(l*2+1)*128 + n)*144 + k] = __bfloat16_as_ushort(lb);
        }
    } else {                               // zero g_pre
        int i = (bid - 1920)*272 + k;
        if (i < 16*H) g_pre[i] = 0.f;
    }
}

// ---------------- K1: kNN + gaussian smearing fused --------------------------
__global__ void knnattr_kernel(const float* __restrict__ ppos, const float* __restrict__ lpos,
                               int n_prot, int n_lig, int n, float step, float coeff)
{
    extern __shared__ float4 spos4[];
    int b = blockIdx.y, tid = threadIdx.x;
    for (int i = tid; i < n; i += blockDim.x) {
        const float* p = (i < n_prot) ? (ppos + ((size_t)b*n_prot + i)*3)
                                      : (lpos + ((size_t)b*n_lig + (i - n_prot))*3);
        spos4[i] = make_float4(p[0], p[1], p[2], 0.f);
    }
    __syncthreads();
    int c = blockIdx.x*blockDim.x + tid;
    if (c >= n) return;
    float4 pc = spos4[c];
    float bd[KNN]; int bi[KNN];
#pragma unroll
    for (int s = 0; s < KNN; ++s) { bd[s] = 3.402823466e38f; bi[s] = 0x7fffffff; }
    float wd = 3.402823466e38f; int wi = 0x7fffffff; int ws = 0;
    for (int j = 0; j < n; ++j) {
        if (j == c) continue;
        float4 pj = spos4[j];
        float dx = pc.x - pj.x, dy = pc.y - pj.y, dz = pc.z - pj.z;
        float d2 = dx*dx + dy*dy + dz*dz;
        if (d2 < wd || (d2 == wd && j < wi)) {
            bd[ws] = d2; bi[ws] = j;
            wd = bd[0]; wi = bi[0]; ws = 0;
#pragma unroll
            for (int s = 1; s < KNN; ++s)
                if (bd[s] > wd || (bd[s] == wd && bi[s] > wi)) { wd = bd[s]; wi = bi[s]; ws = s; }
        }
    }
    size_t base = ((size_t)(b*n + c))*KNN;
    size_t abase = base*GG;
#pragma unroll
    for (int s = 0; s < KNN; ++s) {
        g_nbr[base + s] = b*n + bi[s];
        float d = sqrtf(bd[s]);
#pragma unroll
        for (int g = 0; g < GG; ++g) {
            float t = d - g*step;
            g_attr[abase + s*GG + g] = expf(coeff*t*t);
        }
    }
}

// ---------------- K2: fused embed + A|B (layer 0) ----------------------------
#define ABK 144
#define LDH 152
#define EA_HHI  0
#define EA_HLO  19456
#define EA_FEAT 38912
#define EA_WP   46080
#define EA_WL   60416
#define EA_BIAS 74752
#define EA_SMEM 75776

__global__ void __launch_bounds__(256) embedab_kernel(const float* __restrict__ pfeat,
                                                      const float* __restrict__ lfeat,
                                                      const float* __restrict__ pw, const float* __restrict__ pb,
                                                      const float* __restrict__ lw, const float* __restrict__ lb,
                                                      int n_prot, int n_lig, int n, int Fp, int Fl)
{
    extern __shared__ __align__(16) char she[];
    __nv_bfloat16* sHhi = (__nv_bfloat16*)(she + EA_HHI);
    __nv_bfloat16* sHlo = (__nv_bfloat16*)(she + EA_HLO);
    float* sfeat = (float*)(she + EA_FEAT);
    float* sWp   = (float*)(she + EA_WP);
    float* sWl   = (float*)(she + EA_WL);
    float* sbias = (float*)(she + EA_BIAS);
    int tid = threadIdx.x;
    int nb = blockIdx.x*64;

    for (int i = tid; i < Fp*H; i += 256) sWp[i] = pw[i];
    for (int i = tid; i < Fl*H; i += 256) sWl[i] = lw[i];
    if (tid < 128) sbias[tid] = pb[tid];
    else           sbias[128 + (tid-128)] = lb[tid-128];
    for (int i = tid; i < 64*28; i += 256) {
        int r = i / 28, f = i % 28;
        int node = nb + r, b = node / n, j = node - b*n;
        float v = 0.f;
        if (j < n_prot) { if (f < Fp) v = pfeat[((size_t)b*n_prot + j)*Fp + f]; }
        else            { if (f < Fl) v = lfeat[((size_t)b*n_lig + (j - n_prot))*Fl + f]; }
        sfeat[i] = v;
    }
    __syncthreads();

    for (int i = tid; i < 8192; i += 256) {
        int r = i >> 7, cc = i & 127;
        int node = nb + r, b = node / n, j = node - b*n;
        bool isP = (j < n_prot);
        const float* w = isP ? sWp : sWl;
        float acc = isP ? sbias[cc] : sbias[128 + cc];
        int F = isP ? Fp : Fl;
        for (int f = 0; f < F; ++f) acc += sfeat[r*28 + f]*w[f*H + cc];
        g_h[(size_t)node*H + cc] = acc;
        __nv_bfloat16 hb = __float2bfloat16(acc);
        sHhi[r*LDH + cc] = hb;
        sHlo[r*LDH + cc] = __float2bfloat16(acc - __bfloat162float(hb));
    }
    for (int i = tid; i < 64*24; i += 256) {
        int row = i / 24, k = 128 + (i % 24);
        sHhi[row*LDH + k] = (k == 128) ? __float2bfloat16(1.0f) : __float2bfloat16(0.0f);
        sHlo[row*LDH + k] = __float2bfloat16(0.0f);
    }
    __syncthreads();

    int wrp = tid >> 5;
    int rowg = wrp >> 2, colg = wrp & 3;
    int er = rowg*32, nc = colg*64;
    const __nv_bfloat16* Wh = (const __nv_bfloat16*)g_w1ab;          // layer 0
    const __nv_bfloat16* Wl2 = (const __nv_bfloat16*)g_w1ab + (size_t)256*144;

    wmma::fragment<wmma::accumulator,16,16,16,float> acc[2][4];
#pragma unroll
    for (int i = 0; i < 2; ++i)
#pragma unroll
        for (int j = 0; j < 4; ++j) wmma::fill_fragment(acc[i][j], 0.f);
#pragma unroll
    for (int k0 = 0; k0 < ABK; k0 += 16) {
        wmma::fragment<wmma::matrix_a,16,16,16,__nv_bfloat16,wmma::row_major> ah[2], al[2];
#pragma unroll
        for (int i = 0; i < 2; ++i) {
            wmma::load_matrix_sync(ah[i], sHhi + (er + i*16)*LDH + k0, LDH);
            wmma::load_matrix_sync(al[i], sHlo + (er + i*16)*LDH + k0, LDH);
        }
#pragma unroll
        for (int j = 0; j < 4; ++j) {
            wmma::fragment<wmma::matrix_b,16,16,16,__nv_bfloat16,wmma::col_major> bh, bl;
            wmma::load_matrix_sync(bh, Wh + (size_t)(nc + j*16)*144 + k0, 144);
            wmma::load_matrix_sync(bl, Wl2 + (size_t)(nc + j*16)*144 + k0, 144);
#pragma unroll
            for (int i = 0; i < 2; ++i) {
                wmma::mma_sync(acc[i][j], ah[i], bh, acc[i][j]);
                wmma::mma_sync(acc[i][j], ah[i], bl, acc[i][j]);
                wmma::mma_sync(acc[i][j], al[i], bh, acc[i][j]);
            }
        }
    }
#pragma unroll
    for (int i = 0; i < 2; ++i)
#pragma unroll
        for (int j = 0; j < 4; ++j) {
            int c = nc + j*16;
            float* dstp = (c < 128) ? (g_A + (size_t)(nb + er + i*16)*H + c)
                                    : (g_B + (size_t)(nb + er + i*16)*H + (c - 128));
            wmma::store_matrix_sync(dstp, acc[i][j], H, wmma::mem_row_major);
        }
}

// ---------------- K4: A|B via WMMA (layers 1,2) ------------------------------
__global__ void __launch_bounds__(256) ab_kernel(int l)
{
    __shared__ __align__(16) __nv_bfloat16 sHhi[64*LDH];
    __shared__ __align__(16) __nv_bfloat16 sHlo[64*LDH];
    int tid = threadIdx.x;
    int nb = blockIdx.x*64;
    for (int i = tid; i < 2048; i += 256) {
        int row = i >> 5, k4 = (i & 31)*4;
        float4 hv = *(const float4*)(g_h + (size_t)(nb+row)*H + k4);
        float x[4] = {hv.x, hv.y, hv.z, hv.w};
#pragma unroll
        for (int q = 0; q < 4; ++q) {
            __nv_bfloat16 hb = __float2bfloat16(x[q]);
            sHhi[row*LDH + k4 + q] = hb;
            sHlo[row*LDH + k4 + q] = __float2bfloat16(x[q] - __bfloat162float(hb));
        }
    }
    for (int i = tid; i < 64*24; i += 256) {
        int row = i / 24, k = 128 + (i % 24);
        sHhi[row*LDH + k] = (k == 128) ? __float2bfloat16(1.0f) : __float2bfloat16(0.0f);
        sHlo[row*LDH + k] = __float2bfloat16(0.0f);
    }
    __syncthreads();

    int wrp = tid >> 5;
    int rowg = wrp >> 2, colg = wrp & 3;
    int er = rowg*32, nc = colg*64;
    const __nv_bfloat16* Wh = (const __nv_bfloat16*)g_w1ab + (size_t)(l*2+0)*256*144;
    const __nv_bfloat16* Wl = (const __nv_bfloat16*)g_w1ab + (size_t)(l*2+1)*256*144;

    wmma::fragment<wmma::accumulator,16,16,16,float> acc[2][4];
#pragma unroll
    for (int i = 0; i < 2; ++i)
#pragma unroll
        for (int j = 0; j < 4; ++j) wmma::fill_fragment(acc[i][j], 0.f);
#pragma unroll
    for (int k0 = 0; k0 < ABK; k0 += 16) {
        wmma::fragment<wmma::matrix_a,16,16,16,__nv_bfloat16,wmma::row_major> ah[2], al[2];
#pragma unroll
        for (int i = 0; i < 2; ++i) {
            wmma::load_matrix_sync(ah[i], sHhi + (er + i*16)*LDH + k0, LDH);
            wmma::load_matrix_sync(al[i], sHlo + (er + i*16)*LDH + k0, LDH);
        }
#pragma unroll
        for (int j = 0; j < 4; ++j) {
            wmma::fragment<wmma::matrix_b,16,16,16,__nv_bfloat16,wmma::col_major> bh, bl;
            wmma::load_matrix_sync(bh, Wh + (size_t)(nc + j*16)*144 + k0, 144);
            wmma::load_matrix_sync(bl, Wl + (size_t)(nc + j*16)*144 + k0, 144);
#pragma unroll
            for (int i = 0; i < 2; ++i) {
                wmma::mma_sync(acc[i][j], ah[i], bh, acc[i][j]);
                wmma::mma_sync(acc[i][j], ah[i], bl, acc[i][j]);
                wmma::mma_sync(acc[i][j], al[i], bh, acc[i][j]);
            }
        }
    }
#pragma unroll
    for (int i = 0; i < 2; ++i)
#pragma unroll
        for (int j = 0; j < 4; ++j) {
            int c = nc + j*16;
            float* dstp = (c < 128) ? (g_A + (size_t)(nb + er + i*16)*H + c)
                                    : (g_B + (size_t)(nb + er + i*16)*H + (c - 128));
            wmma::store_matrix_sync(dstp, acc[i][j], H, wmma::mem_row_major);
        }
}

// ---------------- K5: persistent edge kernel, 512 threads --------------------
#define D1_OFF    0
#define LD1 68
#define M1_HI_OFF 34816
#define M1_LO_OFF 69632
#define D2_OFF    34816
#define B_HI_OFF  104448
#define B_LO_OFF  139264
#define W1EH_OFF  174080
#define W1EL_OFF  184320
#define ATTRH_OFF 194560
#define ATTRL_OFF 204800
#define SA_OFF    215040
#define SB2_OFF   217088
#define SINFW_OFF 217600
#define SGATE_OFF 218112
#define SMI_OFF   218624
#define SSRC_OFF  220672
#define RAW_OFF   221184
#define EDGE_SMEM 231424
#define LDAB  136
#define LDATT 40
#define ETH 512

__device__ __forceinline__ void edge_prefetch(unsigned sbase, int t, int tid)
{
    const char* attrp = (const char*)g_attr + (size_t)t*128*GG*4;
    for (int i = tid; i < 640; i += ETH) cp16(sbase + RAW_OFF + i*16, attrp + i*16);
    const char* ap = (const char*)g_A + (size_t)t*4*H*4;
    for (int i = tid; i < 128; i += ETH) cp16(sbase + SA_OFF + i*16, ap + i*16);
    if (tid < 32) cp16(sbase + SSRC_OFF + tid*16, (const char*)g_nbr + (size_t)t*128*4 + tid*16);
    asm volatile("cp.async.commit_group;" ::: "memory");
}

__global__ void __launch_bounds__(ETH,1) edge_kernel(const float* __restrict__ edge_b2,
                                                     const float* __restrict__ inf_w,
                                                     const float* __restrict__ inf_b,
                                                     int l, int ntiles)
{
    extern __shared__ __align__(16) char sh[];
    float* D1 = (float*)(sh + D1_OFF);
    float* D2 = (float*)(sh + D2_OFF);
    __nv_bfloat16* sM1hi = (__nv_bfloat16*)(sh + M1_HI_OFF);
    __nv_bfloat16* sM1lo = (__nv_bfloat16*)(sh + M1_LO_OFF);
    __nv_bfloat16* sBhi  = (__nv_bfloat16*)(sh + B_HI_OFF);
    __nv_bfloat16* sBlo  = (__nv_bfloat16*)(sh + B_LO_OFF);
    __nv_bfloat16* sWeH  = (__nv_bfloat16*)(sh + W1EH_OFF);
    __nv_bfloat16* sWeL  = (__nv_bfloat16*)(sh + W1EL_OFF);
    __nv_bfloat16* sAtH  = (__nv_bfloat16*)(sh + ATTRH_OFF);
    __nv_bfloat16* sAtL  = (__nv_bfloat16*)(sh + ATTRL_OFF);
    float* sAv   = (float*)(sh + SA_OFF);
    float* sb2   = (float*)(sh + SB2_OFF);
    float* sinfw = (float*)(sh + SINFW_OFF);
    float* sgate = (float*)(sh + SGATE_OFF);
    float* smi   = (float*)(sh + SMI_OFF);
    int*   ssrc  = (int*)(sh + SSRC_OFF);
    float* raw   = (float*)(sh + RAW_OFF);

    int tid = threadIdx.x;
    int wrp = tid >> 5;
    unsigned sbase = smem_u32(sh);
    float infb = inf_b[l];

    {
        const uint4* gh = (const uint4*)(g_w2bf + (size_t)(l*2+0)*16384);
        const uint4* gl = (const uint4*)(g_w2bf + (size_t)(l*2+1)*16384);
        for (int i = tid; i < 2048; i += ETH) {
            int row = i >> 4, q = i & 15;
            cp16(sbase + B_HI_OFF + row*272 + q*16, gh + row*16 + q);
            cp16(sbase + B_LO_OFF + row*272 + q*16, gl + row*16 + q);
        }
        const char* gwh = (const char*)(g_w1ebf + (size_t)(l*2+0)*4096);
        const char* gwl = (const char*)(g_w1ebf + (size_t)(l*2+1)*4096);
        for (int i = tid; i < 512; i += ETH) {
            int nr = i >> 2, q = i & 3;
            cp16(sbase + W1EH_OFF + nr*80 + q*16, gwh + nr*64 + q*16);
            cp16(sbase + W1EL_OFF + nr*80 + q*16, gwl + nr*64 + q*16);
        }
        asm volatile("cp.async.commit_group;" ::: "memory");
        if (tid < H) { sb2[tid] = edge_b2[l*H+tid]; sinfw[tid] = inf_w[l*H+tid]; }
    }
    int t = blockIdx.x;
    if (t < ntiles) edge_prefetch(sbase, t, tid);
    asm volatile("cp.async.wait_group 0;" ::: "memory");
    __syncthreads();

    for (; t < ntiles; t += gridDim.x) {
        int d0 = t * 4;

        for (int i = tid; i < 2048; i += ETH) {
            int el = i >> 4, k2 = i & 15;
            int k = k2*2;
            float f0 = (k   < GG) ? raw[el*GG + k]     : 0.f;
            float f1 = (k+1 < GG) ? raw[el*GG + k + 1] : 0.f;
            __nv_bfloat16 h0 = __float2bfloat16(f0), h1 = __float2bfloat16(f1);
            __nv_bfloat16 l0 = __float2bfloat16(f0 - __bfloat162float(h0));
            __nv_bfloat16 l1 = __float2bfloat16(f1 - __bfloat162float(h1));
            *(unsigned*)((char*)sAtH + el*80 + k2*4) =
                ((unsigned)__bfloat16_as_ushort(h1) << 16) | __bfloat16_as_ushort(h0);
            *(unsigned*)((char*)sAtL + el*80 + k2*4) =
                ((unsigned)__bfloat16_as_ushort(l1) << 16) | __bfloat16_as_ushort(l0);
        }
        for (int i = tid; i < 512; i += ETH) smi[i] = 0.f;
        if (tid < 128) sgate[tid] = infb;
        __syncthreads();

        for (int h = 0; h < 2; ++h) {
            {
                int er = (wrp & 7)*16, jb = (wrp >> 3)*2;
                wmma::fragment<wmma::accumulator,16,16,16,float> a1[2];
#pragma unroll
                for (int j = 0; j < 2; ++j) wmma::fill_fragment(a1[j], 0.f);
#pragma unroll
                for (int k0 = 0; k0 < 32; k0 += 16) {
                    wmma::fragment<wmma::matrix_a,16,16,16,__nv_bfloat16,wmma::row_major> ah, al;
                    wmma::load_matrix_sync(ah, sAtH + er*LDATT + k0, LDATT);
                    wmma::load_matrix_sync(al, sAtL + er*LDATT + k0, LDATT);
#pragma unroll
                    for (int j = 0; j < 2; ++j) {
                        wmma::fragment<wmma::matrix_b,16,16,16,__nv_bfloat16,wmma::col_major> bh, bl;
                        wmma::load_matrix_sync(bh, sWeH + (h*64 + (jb+j)*16)*LDATT + k0, LDATT);
                        wmma::load_matrix_sync(bl, sWeL + (h*64 + (jb+j)*16)*LDATT + k0, LDATT);
                        wmma::mma_sync(a1[j], ah, bh, a1[j]);
                        wmma::mma_sync(a1[j], ah, bl, a1[j]);
                        wmma::mma_sync(a1[j], al, bh, a1[j]);
                    }
                }
#pragma unroll
                for (int j = 0; j < 2; ++j)
                    wmma::store_matrix_sync(D1 + er*LD1 + (jb+j)*16, a1[j], LD1, wmma::mem_row_major);
            }
            __syncthreads();
            {
                int e = tid >> 2, q = tid & 3;
                int srcA = ssrc[e];
                const float4* Brow = (const float4*)(g_B + (size_t)srcA*H);
                const float* sAd = sAv + (e>>5)*H;
#pragma unroll
                for (int i4 = 0; i4 < 4; ++i4) {
                    int kl = q*16 + i4*4;
                    int kg = h*64 + kl;
                    float4 bv = Brow[kg >> 2];
                    float4 gv = *(const float4*)(D1 + e*LD1 + kl);
                    float x0 = fmaxf(gv.x + sAd[kg]   + bv.x, 0.f);
                    float x1 = fmaxf(gv.y + sAd[kg+1] + bv.y, 0.f);
                    float x2 = fmaxf(gv.z + sAd[kg+2] + bv.z, 0.f);
                    float x3 = fmaxf(gv.w + sAd[kg+3] + bv.w, 0.f);
                    __nv_bfloat16 h0 = __float2bfloat16(x0), h1 = __float2bfloat16(x1);
                    __nv_bfloat16 h2 = __float2bfloat16(x2), h3 = __float2bfloat16(x3);
                    __nv_bfloat16 l0 = __float2bfloat16(x0 - __bfloat162float(h0));
                    __nv_bfloat16 l1 = __float2bfloat16(x1 - __bfloat162float(h1));
                    __nv_bfloat16 l2 = __float2bfloat16(x2 - __bfloat162float(h2));
                    __nv_bfloat16 l3 = __float2bfloat16(x3 - __bfloat162float(h3));
                    unsigned hi01 = ((unsigned)__bfloat16_as_ushort(h1) << 16) | __bfloat16_as_ushort(h0);
                    unsigned hi23 = ((unsigned)__bfloat16_as_ushort(h3) << 16) | __bfloat16_as_ushort(h2);
                    unsigned lo01 = ((unsigned)__bfloat16_as_ushort(l1) << 16) | __bfloat16_as_ushort(l0);
                    unsigned lo23 = ((unsigned)__bfloat16_as_ushort(l3) << 16) | __bfloat16_as_ushort(l2);
                    unsigned boff = e*272 + kg*2;
                    *(uint2*)((char*)sM1hi + boff) = make_uint2(hi01, hi23);
                    *(uint2*)((char*)sM1lo + boff) = make_uint2(lo01, lo23);
                }
            }
            __syncthreads();
        }

        int tn = t + gridDim.x;
        if (tn < ntiles) edge_prefetch(sbase, tn, tid);

        {
            int rg = wrp & 3, cgf = wrp >> 2;
            int er = rg*32, nc = cgf*32;
            wmma::fragment<wmma::accumulator,16,16,16,float> acc[2][2];
#pragma unroll
            for (int i = 0; i < 2; ++i)
#pragma unroll
                for (int j = 0; j < 2; ++j) wmma::fill_fragment(acc[i][j], 0.f);
#pragma unroll
            for (int k0 = 0; k0 < 128; k0 += 16) {
                wmma::fragment<wmma::matrix_a,16,16,16,__nv_bfloat16,wmma::row_major> ah[2], al[2];
                wmma::fragment<wmma::matrix_b,16,16,16,__nv_bfloat16,wmma::col_major> bh[2], bl[2];
#pragma unroll
                for (int i = 0; i < 2; ++i) {
                    wmma::load_matrix_sync(ah[i], sM1hi + (er + i*16)*LDAB + k0, LDAB);
                    wmma::load_matrix_sync(al[i], sM1lo + (er + i*16)*LDAB + k0, LDAB);
                }
#pragma unroll
                for (int j = 0; j < 2; ++j) {
                    wmma::load_matrix_sync(bh[j], sBhi + (nc + j*16)*LDAB + k0, LDAB);
                    wmma::load_matrix_sync(bl[j], sBlo + (nc + j*16)*LDAB + k0, LDAB);
                }
#pragma unroll
                for (int i = 0; i < 2; ++i)
#pragma unroll
                    for (int j = 0; j < 2; ++j) {
                        wmma::mma_sync(acc[i][j], ah[i], bh[j], acc[i][j]);
                        wmma::mma_sync(acc[i][j], ah[i], bl[j], acc[i][j]);
                        wmma::mma_sync(acc[i][j], al[i], bh[j], acc[i][j]);
                    }
            }
            __syncthreads();
#pragma unroll
            for (int i = 0; i < 2; ++i)
#pragma unroll
                for (int j = 0; j < 2; ++j)
                    wmma::store_matrix_sync(D2 + (er + i*16)*132 + nc + j*16, acc[i][j],
                                            132, wmma::mem_row_major);
        }
        __syncthreads();

        // register epilogue: bias + relu + gate logit, then scale + warp-reduce
        {
            int e = tid >> 2, q = tid & 3, c0 = q*32;
            float v[32];
            float p = 0.f;
#pragma unroll
            for (int c = 0; c < 32; ++c) {
                float x = D2[e*132 + c0 + c] + sb2[c0 + c];
                x = fmaxf(x, 0.f);
                v[c] = x;
                p += x * sinfw[c0 + c];
            }
            atomicAdd(&sgate[e], p);
            __syncthreads();
            if (tid < 128) sgate[tid] = 1.f/(1.f + expf(-sgate[tid]));
            __syncthreads();
            float gt = sgate[e];
#pragma unroll
            for (int c = 0; c < 32; ++c) v[c] *= gt;
#pragma unroll
            for (int off = 4; off <= 16; off <<= 1)
#pragma unroll
                for (int c = 0; c < 32; ++c) v[c] += __shfl_xor_sync(0xffffffffu, v[c], off);
            if ((tid & 31) < 4) {
                int d = wrp >> 2;
#pragma unroll
                for (int c = 0; c < 32; ++c) atomicAdd(&smi[d*H + c0 + c], v[c]);
            }
        }
        __syncthreads();
        for (int i = tid; i < 4*H; i += ETH) g_mi[(size_t)d0*H + i] = smi[i];
        asm volatile("cp.async.wait_group 0;" ::: "memory");
        __syncthreads();
    }
}

// ---------------- K6: node MLP via WMMA (bias-in-K), 64-node tiles -----------
#define NLDZ 280
#define NLDU 152
#define NZHI_OFF 0
#define NZLO_OFF 35840
#define ND1_OFF  35840
#define NUHI_OFF 71680
#define NULO_OFF 91136
#define ND2_OFF  0
#define NODE_SMEM 110592

__global__ void __launch_bounds__(256) node_kernel(int l)
{
    extern __shared__ __align__(16) char shn[];
    __nv_bfloat16* zHi = (__nv_bfloat16*)(shn + NZHI_OFF);
    __nv_bfloat16* zLo = (__nv_bfloat16*)(shn + NZLO_OFF);
    float* D1 = (float*)(shn + ND1_OFF);
    __nv_bfloat16* uHi = (__nv_bfloat16*)(shn + NUHI_OFF);
    __nv_bfloat16* uLo = (__nv_bfloat16*)(shn + NULO_OFF);
    float* D2 = (float*)(shn + ND2_OFF);

    int tid = threadIdx.x;
    int nb = blockIdx.x*64;

    for (int i = tid; i < 2048; i += 256) {
        int row = i >> 5, k4 = (i & 31)*4;
        float4 mv = *(const float4*)(g_mi + (size_t)(nb+row)*H + k4);
        float4 hv = *(const float4*)(g_h  + (size_t)(nb+row)*H + k4);
        float xm[4] = {mv.x, mv.y, mv.z, mv.w};
        float xh[4] = {hv.x, hv.y, hv.z, hv.w};
#pragma unroll
        for (int q = 0; q < 4; ++q) {
            __nv_bfloat16 mb = __float2bfloat16(xm[q]);
            zHi[row*NLDZ + k4 + q] = mb;
            zLo[row*NLDZ + k4 + q] = __float2bfloat16(xm[q] - __bfloat162float(mb));
            __nv_bfloat16 hb = __float2bfloat16(xh[q]);
            zHi[row*NLDZ + 128 + k4 + q] = hb;
            zLo[row*NLDZ + 128 + k4 + q] = __float2bfloat16(xh[q] - __bfloat162float(hb));
        }
    }
    for (int i = tid; i < 64*16; i += 256) {
        int row = i >> 4, k = 256 + (i & 15);
        zHi[row*NLDZ + k] = (k == 256) ? __float2bfloat16(1.0f) : __float2bfloat16(0.0f);
        zLo[row*NLDZ + k] = __float2bfloat16(0.0f);
    }
    __syncthreads();

    int wrp = tid >> 5;
    int rowg = wrp >> 2, colg = wrp & 3;
    int er = rowg*32, nc = colg*32;
    const __nv_bfloat16* W1h = (const __nv_bfloat16*)g_w1nb + (size_t)(l*2+0)*128*272;
    const __nv_bfloat16* W1l = (const __nv_bfloat16*)g_w1nb + (size_t)(l*2+1)*128*272;

    wmma::fragment<wmma::accumulator,16,16,16,float> acc[2][2];
#pragma unroll
    for (int i = 0; i < 2; ++i)
#pragma unroll
        for (int j = 0; j < 2; ++j) wmma::fill_fragment(acc[i][j], 0.f);
#pragma unroll
    for (int k0 = 0; k0 < 272; k0 += 16) {
        wmma::fragment<wmma::matrix_a,16,16,16,__nv_bfloat16,wmma::row_major> ah[2], al[2];
#pragma unroll
        for (int i = 0; i < 2; ++i) {
            wmma::load_matrix_sync(ah[i], zHi + (er + i*16)*NLDZ + k0, NLDZ);
            wmma::load_matrix_sync(al[i], zLo + (er + i*16)*NLDZ + k0, NLDZ);
        }
#pragma unroll
        for (int j = 0; j < 2; ++j) {
            wmma::fragment<wmma::matrix_b,16,16,16,__nv_bfloat16,wmma::col_major> bh, bl;
            wmma::load_matrix_sync(bh, W1h + (size_t)(nc + j*16)*272 + k0, 272);
            wmma::load_matrix_sync(bl, W1l + (size_t)(nc + j*16)*272 + k0, 272);
#pragma unroll
            for (int i = 0; i < 2; ++i) {
                wmma::mma_sync(acc[i][j], ah[i], bh, acc[i][j]);
                wmma::mma_sync(acc[i][j], ah[i], bl, acc[i][j]);
                wmma::mma_sync(acc[i][j], al[i], bh, acc[i][j]);
            }
        }
    }
    __syncthreads();
#pragma unroll
    for (int i = 0; i < 2; ++i)
#pragma unroll
        for (int j = 0; j < 2; ++j)
            wmma::store_matrix_sync(D1 + (er + i*16)*132 + nc + j*16, acc[i][j],
                                    132, wmma::mem_row_major);
    __syncthreads();

    for (int i = tid; i < 2048; i += 256) {
        int row = i >> 5, k4 = (i & 31)*4;
        float4 uv = *(const float4*)(D1 + row*132 + k4);
        float x[4] = {fmaxf(uv.x,0.f), fmaxf(uv.y,0.f), fmaxf(uv.z,0.f), fmaxf(uv.w,0.f)};
#pragma unroll
        for (int q = 0; q < 4; ++q) {
            __nv_bfloat16 ub = __float2bfloat16(x[q]);
            uHi[row*NLDU + k4 + q] = ub;
            uLo[row*NLDU + k4 + q] = __float2bfloat16(x[q] - __bfloat162float(ub));
        }
    }
    for (int i = tid; i < 64*16; i += 256) {
        int row = i >> 4, k = 128 + (i & 15);
        uHi[row*NLDU + k] = (k == 128) ? __float2bfloat16(1.0f) : __float2bfloat16(0.0f);
        uLo[row*NLDU + k] = __float2bfloat16(0.0f);
    }
    __syncthreads();

    const __nv_bfloat16* W2h = (const __nv_bfloat16*)g_w2nb + (size_t)(l*2+0)*128*144;
    const __nv_bfloat16* W2l = (const __nv_bfloat16*)g_w2nb + (size_t)(l*2+1)*128*144;
#pragma unroll
    for (int i = 0; i < 2; ++i)
#pragma unroll
        for (int j = 0; j < 2; ++j) wmma::fill_fragment(acc[i][j], 0.f);
#pragma unroll
    for (int k0 = 0; k0 < 144; k0 += 16) {
        wmma::fragment<wmma::matrix_a,16,16,16,__nv_bfloat16,wmma::row_major> ah[2], al[2];
#pragma unroll
        for (int i = 0; i < 2; ++i) {
            wmma::load_matrix_sync(ah[i], uHi + (er + i*16)*NLDU + k0, NLDU);
            wmma::load_matrix_sync(al[i], uLo + (er + i*16)*NLDU + k0, NLDU);
        }
#pragma unroll
        for (int j = 0; j < 2; ++j) {
            wmma::fragment<wmma::matrix_b,16,16,16,__nv_bfloat16,wmma::col_major> bh, bl;
            wmma::load_matrix_sync(bh, W2h + (size_t)(nc + j*16)*144 + k0, 144);
            wmma::load_matrix_sync(bl, W2l + (size_t)(nc + j*16)*144 + k0, 144);
#pragma unroll
            for (int i = 0; i < 2; ++i) {
                wmma::mma_sync(acc[i][j], ah[i], bh, acc[i][j]);
                wmma::mma_sync(acc[i][j], ah[i], bl, acc[i][j]);
                wmma::mma_sync(acc[i][j], al[i], bh, acc[i][j]);
            }
        }
    }
#pragma unroll
    for (int i = 0; i < 2; ++i)
#pragma unroll
        for (int j = 0; j < 2; ++j)
            wmma::store_matrix_sync(D2 + (er + i*16)*132 + nc + j*16, acc[i][j],
                                    132, wmma::mem_row_major);
    __syncthreads();

    for (int i = tid; i < 2048; i += 256) {
        int row = i >> 5, k4 = (i & 31)*4;
        float4 ov = *(const float4*)(D2 + row*132 + k4);
        float4* hp = (float4*)(g_h + (size_t)(nb+row)*H + k4);
        float4 hv = *hp;
        hv.x += ov.x; hv.y += ov.y; hv.z += ov.z; hv.w += ov.w;
        *hp = hv;
    }
}

// ---------------- K7/K8 ------------------------------------------------------
__global__ void pool_kernel(int n)
{
    int b = blockIdx.x >> 4, s = blockIdx.x & 15;
    int c = threadIdx.x;
    float acc = 0.f;
    for (int i = s; i < n; i += 16) acc += g_h[((size_t)b*n + i)*H + c];
    atomicAdd(&g_pre[b*H + c], acc);
}

__global__ void out_kernel(const float* __restrict__ w1, const float* __restrict__ b1,
                           const float* __restrict__ w2, const float* __restrict__ b2,
                           const int* __restrict__ kind, float* __restrict__ out, int B)
{
    __shared__ float sU[H]; __shared__ float so[3];
    int t = threadIdx.x;
    for (int b = 0; b < B; ++b) {
        float x = b1[t];
        for (int k = 0; k < H; ++k) x += g_pre[b*H + k]*w1[k*H + t];
        float sp = (x > 0.f) ? x + log1pf(expf(-x)) : log1pf(expf(x));
        sU[t] = sp - 0.6931471805599453f;
        __syncthreads();
        if (t < 3) { float s = b2[t]; for (int k = 0; k < H; ++k) s += sU[k]*w2[k*3 + t]; so[t] = s; }
        __syncthreads();
        if (t == 0) out[b] = so[kind[b] - 1];
        __syncthreads();
    }
}

// ---------------- host ------------------------------------------------------
extern "C" void kernel_launch(void* const* d_in, const int* in_sizes, int n_in,
                              void* d_out, int out_size)
{
    const float* protein_pos  = (const float*)d_in[0];
    const float* protein_feat = (const float*)d_in[1];
    const float* ligand_pos   = (const float*)d_in[2];
    const float* ligand_feat  = (const float*)d_in[3];
    const int*   output_kind  = (const int*)d_in[6];
    const float* prot_w = (const float*)d_in[7];  const float* prot_b = (const float*)d_in[8];
    const float* lig_w  = (const float*)d_in[9];  const float* lig_b  = (const float*)d_in[10];
    const float* edge_w1 = (const float*)d_in[11]; const float* edge_b1 = (const float*)d_in[12];
    const float* edge_w2 = (const float*)d_in[13]; const float* edge_b2 = (const float*)d_in[14];
    const float* inf_w   = (const float*)d_in[15]; const float* inf_b   = (const float*)d_in[16];
    const float* node_w1 = (const float*)d_in[17]; const float* node_b1 = (const float*)d_in[18];
    const float* node_w2 = (const float*)d_in[19]; const float* node_b2 = (const float*)d_in[20];
    const float* out_w1  = (const float*)d_in[21]; const float* out_b1  = (const float*)d_in[22];
    const float* out_w2  = (const float*)d_in[23]; const float* out_b2  = (const float*)d_in[24];
    float* out = (float*)d_out;

    int Np = in_sizes[0]/3, Nl = in_sizes[2]/3;
    int B  = in_sizes[6];
    int Fp = in_sizes[1]/Np, Fl = in_sizes[3]/Nl;
    int n_prot = Np/B, n_lig = Nl/B;
    int n = n_prot + n_lig;
    int N = Np + Nl;
    int E = N*KNN;
    int ntiles = E/128;

    int nsm = 148;
    cudaDeviceGetAttribute(&nsm, cudaDevAttrMultiProcessorCount, 0);

    cudaFuncSetAttribute(edge_kernel, cudaFuncAttributeMaxDynamicSharedMemorySize, EDGE_SMEM);
    cudaFuncSetAttribute(node_kernel, cudaFuncAttributeMaxDynamicSharedMemorySize, NODE_SMEM);
    cudaFuncSetAttribute(embedab_kernel, cudaFuncAttributeMaxDynamicSharedMemorySize, EA_SMEM);

    float step  = 10.0f/19.0f;
    float coeff = -0.5f/(step*step);

    // launch order chosen so edge_kernel is launch #4 (ncu capture slot)
    prep_kernel<<<1928, 272>>>(edge_w2, edge_w1, edge_b1, node_w1, node_b1, node_w2, node_b2);
    knnattr_kernel<<<dim3((n + 127)/128, B), 128, n*(int)sizeof(float4)>>>(
        protein_pos, ligand_pos, n_prot, n_lig, n, step, coeff);
    embedab_kernel<<<N/64, 256, EA_SMEM>>>(protein_feat, ligand_feat,
                                           prot_w, prot_b, lig_w, lig_b,
                                           n_prot, n_lig, n, Fp, Fl);
    for (int l = 0; l < 3; ++l) {
        edge_kernel<<<nsm, ETH, EDGE_SMEM>>>(edge_b2, inf_w, inf_b, l, ntiles);
        node_kernel<<<N/64, 256, NODE_SMEM>>>(l);
        if (l < 2) ab_kernel<<<N/64, 256>>>(l + 1);
    }

    pool_kernel<<<B*16, 128>>>(n);
    out_kernel<<<1, 128>>>(out_w1, out_b1, out_w2, out_b2, output_kind, out, B);
}